// round 1
// baseline (speedup 1.0000x reference)
#include <cuda_runtime.h>
#include <math.h>

#define NN 50000
#define NE 800000
#define NT (NN + NE)   // edges incl. self loops
#define MAXC 256

// ---------------- scratch (static device globals; allowed) ----------------
__device__ float g_bufA[NN * MAXC];   // 51.2 MB
__device__ float g_bufB[NN * MAXC];   // 51.2 MB
__device__ float g_bufC[NN * MAXC];   // 51.2 MB
__device__ float g_ssrc[NN * 4];
__device__ float g_sdst[NN * 4];
__device__ float g_z[NN * 4];
__device__ float g_expe[(size_t)NT * 4];  // 13.6 MB

// ---------------- tiled SGEMM: C = act(A[M,K] @ W[K,N] + bias) -------------
// 64x64 tile, BK=16, 256 threads, 4x4 microtile. N % 64 == 0, K % 16 == 0.
__global__ void sgemm_kernel(const float* __restrict__ A,
                             const float* __restrict__ W,
                             const float* __restrict__ bias,
                             float* __restrict__ C,
                             int M, int K, int Ncols, int act /*0 none,1 relu*/) {
    __shared__ float As[16][64];
    __shared__ float Ws[16][64];
    const int tid = threadIdx.x;
    const int tx = tid & 15, ty = tid >> 4;
    const int m0 = blockIdx.y * 64, n0 = blockIdx.x * 64;

    const int ar = tid >> 2, ac = (tid & 3) * 4;   // A-tile loader coords
    const int wr = tid >> 4, wc = (tid & 15) * 4;  // W-tile loader coords

    float acc[4][4] = {};

    for (int k0 = 0; k0 < K; k0 += 16) {
        float4 av = make_float4(0.f, 0.f, 0.f, 0.f);
        if (m0 + ar < M)
            av = *(const float4*)(A + (size_t)(m0 + ar) * K + k0 + ac);
        As[ac + 0][ar] = av.x;
        As[ac + 1][ar] = av.y;
        As[ac + 2][ar] = av.z;
        As[ac + 3][ar] = av.w;

        float4 wv = *(const float4*)(W + (size_t)(k0 + wr) * Ncols + n0 + wc);
        *(float4*)&Ws[wr][wc] = wv;
        __syncthreads();

#pragma unroll
        for (int kk = 0; kk < 16; kk++) {
            float4 a = *(const float4*)&As[kk][ty * 4];
            float4 b = *(const float4*)&Ws[kk][tx * 4];
            float am[4] = {a.x, a.y, a.z, a.w};
            float bm[4] = {b.x, b.y, b.z, b.w};
#pragma unroll
            for (int i = 0; i < 4; i++)
#pragma unroll
                for (int j = 0; j < 4; j++)
                    acc[i][j] += am[i] * bm[j];
        }
        __syncthreads();
    }

    float4 bb = make_float4(0.f, 0.f, 0.f, 0.f);
    if (bias) bb = *(const float4*)(bias + n0 + tx * 4);

#pragma unroll
    for (int i = 0; i < 4; i++) {
        int m = m0 + ty * 4 + i;
        if (m >= M) break;
        float4 v;
        v.x = acc[i][0] + bb.x;
        v.y = acc[i][1] + bb.y;
        v.z = acc[i][2] + bb.z;
        v.w = acc[i][3] + bb.w;
        if (act) {
            v.x = fmaxf(v.x, 0.f); v.y = fmaxf(v.y, 0.f);
            v.z = fmaxf(v.z, 0.f); v.w = fmaxf(v.w, 0.f);
        }
        *(float4*)(C + (size_t)m * Ncols + n0 + tx * 4) = v;
    }
}

// ---------------- per-node attention scores: warp per (n,h), D=64 ----------
template <int H>
__global__ void attn_scores_kernel(const float* __restrict__ xh,
                                   const float* __restrict__ a_src,
                                   const float* __restrict__ a_dst,
                                   float* __restrict__ ssrc,
                                   float* __restrict__ sdst) {
    int warp = (blockIdx.x * blockDim.x + threadIdx.x) >> 5;
    int lane = threadIdx.x & 31;
    if (warp >= NN * H) return;
    int n = warp / H, h = warp % H;
    const float* row = xh + (size_t)n * H * 64 + h * 64;
    float x0 = row[lane], x1 = row[lane + 32];
    float ps = x0 * a_src[h * 64 + lane] + x1 * a_src[h * 64 + lane + 32];
    float pd = x0 * a_dst[h * 64 + lane] + x1 * a_dst[h * 64 + lane + 32];
#pragma unroll
    for (int o = 16; o; o >>= 1) {
        ps += __shfl_xor_sync(0xffffffffu, ps, o);
        pd += __shfl_xor_sync(0xffffffffu, pd, o);
    }
    if (lane == 0) { ssrc[warp] = ps; sdst[warp] = pd; }
}

// ---------------- edge pass 1: exp(leaky_relu) + segment-sum z -------------
template <int H>
__global__ void edge_softmax_num(const int* __restrict__ ei,
                                 const float* __restrict__ ssrc,
                                 const float* __restrict__ sdst,
                                 float* __restrict__ expe,
                                 float* __restrict__ z) {
    int e = blockIdx.x * blockDim.x + threadIdx.x;
    if (e >= NT) return;
    int s, d;
    if (e < NE) { s = ei[e]; d = ei[NE + e]; }
    else        { s = d = e - NE; }
#pragma unroll
    for (int h = 0; h < H; h++) {
        float v = ssrc[s * H + h] + sdst[d * H + h];
        v = v > 0.f ? v : 0.2f * v;           // leaky_relu 0.2
        v = expf(v);
        expe[(size_t)e * H + h] = v;
        atomicAdd(&z[d * H + h], v);
    }
}

// ---------------- edge pass 2: out[dst] += xh[src] * alpha -----------------
template <int H, int EPB>
__global__ void edge_aggregate(const int* __restrict__ ei,
                               const float* __restrict__ xh,
                               const float* __restrict__ expe,
                               const float* __restrict__ z,
                               float* __restrict__ out) {
    const int HD = H * 64;
    int el = threadIdx.x / HD;
    int t  = threadIdx.x % HD;
    int e  = blockIdx.x * EPB + el;
    if (e >= NT) return;
    int s, d;
    if (e < NE) { s = ei[e]; d = ei[NE + e]; }
    else        { s = d = e - NE; }
    int h = t >> 6;
    float alpha = expe[(size_t)e * H + h] / z[d * H + h];
    float v = xh[(size_t)s * HD + t] * alpha;
    atomicAdd(&out[(size_t)d * HD + t], v);
}

// ---------------- finalize kernels -----------------------------------------
__global__ void final_concat_elu(float* __restrict__ io,
                                 const float* __restrict__ b, int C) {
    int i = blockIdx.x * blockDim.x + threadIdx.x;
    if (i >= NN * C) return;
    float v = io[i] + b[i % C];
    io[i] = v > 0.f ? v : expm1f(v);
}

__global__ void final_mean2_elu(const float* __restrict__ acc,
                                const float* __restrict__ b,
                                float* __restrict__ out) {
    int i = blockIdx.x * blockDim.x + threadIdx.x;
    if (i >= NN * 64) return;
    int n = i >> 6, d = i & 63;
    float v = 0.5f * (acc[n * 128 + d] + acc[n * 128 + 64 + d]) + b[d];
    out[i] = v > 0.f ? v : expm1f(v);
}

__global__ void final_out_kernel(const float* __restrict__ acc,
                                 const float* __restrict__ b,
                                 float* __restrict__ out) {
    int i = blockIdx.x * blockDim.x + threadIdx.x;
    if (i >= NN * 64) return;
    out[i] = acc[i] + b[i & 63];
}

// ---------------------------------------------------------------------------
static inline void run_gemm(const float* A, const float* W, const float* bias,
                            float* C, int M, int K, int Ncols, int act) {
    dim3 grid(Ncols / 64, (M + 63) / 64);
    sgemm_kernel<<<grid, 256>>>(A, W, bias, C, M, K, Ncols, act);
}

extern "C" void kernel_launch(void* const* d_in, const int* in_sizes, int n_in,
                              void* d_out, int out_size) {
    const float* x    = (const float*)d_in[0];
    const int*   ei   = (const int*)d_in[1];
    const float* w1   = (const float*)d_in[2];
    const float* b1   = (const float*)d_in[3];
    const float* w2   = (const float*)d_in[4];
    const float* b2   = (const float*)d_in[5];
    const float* g1w  = (const float*)d_in[6];
    const float* g1as = (const float*)d_in[7];
    const float* g1ad = (const float*)d_in[8];
    const float* g1b  = (const float*)d_in[9];
    const float* g2w  = (const float*)d_in[10];
    const float* g2as = (const float*)d_in[11];
    const float* g2ad = (const float*)d_in[12];
    const float* g2b  = (const float*)d_in[13];
    const float* g3w  = (const float*)d_in[14];
    const float* g3as = (const float*)d_in[15];
    const float* g3ad = (const float*)d_in[16];
    const float* g3b  = (const float*)d_in[17];
    float* out = (float*)d_out;

    float *bufA, *bufB, *bufC, *ssrc, *sdst, *z, *expe;
    cudaGetSymbolAddress((void**)&bufA, g_bufA);
    cudaGetSymbolAddress((void**)&bufB, g_bufB);
    cudaGetSymbolAddress((void**)&bufC, g_bufC);
    cudaGetSymbolAddress((void**)&ssrc, g_ssrc);
    cudaGetSymbolAddress((void**)&sdst, g_sdst);
    cudaGetSymbolAddress((void**)&z, g_z);
    cudaGetSymbolAddress((void**)&expe, g_expe);

    const int M = NN;

    // ---------------- MLP ----------------
    run_gemm(x,    w1, b1, bufC, M, 256, 128, 1);   // h0 = relu(x@w1+b1)
    run_gemm(bufC, w2, b2, bufB, M, 128, 128, 1);   // h1 = relu(h0@w2+b2)

    // ---------------- GAT1: H=4, D=64, concat, in=bufB(128) -----------------
    run_gemm(bufB, g1w, nullptr, bufA, M, 128, 256, 0);          // xh -> bufA
    {
        int warps = NN * 4;
        attn_scores_kernel<4><<<(warps * 32 + 255) / 256, 256>>>(bufA, g1as, g1ad, ssrc, sdst);
        cudaMemsetAsync(z, 0, (size_t)NN * 4 * sizeof(float));
        edge_softmax_num<4><<<(NT + 255) / 256, 256>>>(ei, ssrc, sdst, expe, z);
        cudaMemsetAsync(bufC, 0, (size_t)NN * 256 * sizeof(float));
        edge_aggregate<4, 1><<<NT, 256>>>(ei, bufA, expe, z, bufC);
        final_concat_elu<<<(NN * 256 + 255) / 256, 256>>>(bufC, g1b, 256);  // out1 in bufC
    }

    // ---------------- GAT2: H=2, D=64, mean, in=bufC(256) -------------------
    run_gemm(bufC, g2w, nullptr, bufB, M, 256, 128, 0);          // xh -> bufB
    {
        int warps = NN * 2;
        attn_scores_kernel<2><<<(warps * 32 + 255) / 256, 256>>>(bufB, g2as, g2ad, ssrc, sdst);
        cudaMemsetAsync(z, 0, (size_t)NN * 2 * sizeof(float));
        edge_softmax_num<2><<<(NT + 255) / 256, 256>>>(ei, ssrc, sdst, expe, z);
        cudaMemsetAsync(bufA, 0, (size_t)NN * 128 * sizeof(float));
        edge_aggregate<2, 2><<<(NT + 1) / 2, 256>>>(ei, bufB, expe, z, bufA);
        final_mean2_elu<<<(NN * 64 + 255) / 256, 256>>>(bufA, g2b, bufC);   // h3 in bufC[N,64]
    }

    // ---------------- GAT3: H=1, D=64, mean(identity), in=bufC(64) ----------
    run_gemm(bufC, g3w, nullptr, bufB, M, 64, 64, 0);            // xh -> bufB
    {
        int warps = NN * 1;
        attn_scores_kernel<1><<<(warps * 32 + 255) / 256, 256>>>(bufB, g3as, g3ad, ssrc, sdst);
        cudaMemsetAsync(z, 0, (size_t)NN * 1 * sizeof(float));
        edge_softmax_num<1><<<(NT + 255) / 256, 256>>>(ei, ssrc, sdst, expe, z);
        cudaMemsetAsync(bufA, 0, (size_t)NN * 64 * sizeof(float));
        edge_aggregate<1, 4><<<(NT + 3) / 4, 256>>>(ei, bufB, expe, z, bufA);
        final_out_kernel<<<(NN * 64 + 255) / 256, 256>>>(bufA, g3b, out);
    }
}

// round 3
// speedup vs baseline: 2.0101x; 2.0101x over previous
#include <cuda_runtime.h>
#include <math.h>

#define NN 50000
#define NE 800000
#define NT (NN + NE)   // edges incl. self loops
#define MAXC 256

// ---------------- scratch (static device globals; allowed) ----------------
__device__ float g_bufA[NN * MAXC];   // 51.2 MB
__device__ float g_bufB[NN * MAXC];   // 51.2 MB
__device__ float g_bufC[NN * MAXC];   // 51.2 MB
__device__ float g_ssrc[NN * 4];
__device__ float g_sdst[NN * 4];
__device__ float g_z[NN * 4];
__device__ float g_expe[(size_t)NT * 4];  // 13.6 MB

// ---------------- vectorized global reductions (sm_90+) --------------------
__device__ __forceinline__ void red_add4(float* p, float4 v) {
    asm volatile("red.global.add.v4.f32 [%0], {%1,%2,%3,%4};"
                 :: "l"(p), "f"(v.x), "f"(v.y), "f"(v.z), "f"(v.w) : "memory");
}
__device__ __forceinline__ void red_add2(float* p, float2 v) {
    asm volatile("red.global.add.v2.f32 [%0], {%1,%2};"
                 :: "l"(p), "f"(v.x), "f"(v.y) : "memory");
}

// ---------------- big tiled SGEMM: 128x128 tile, BK=8, 8x8 microtile -------
// 256 threads. Requires N % 128 == 0, K % 8 == 0. M guarded.
__global__ void sgemm128_kernel(const float* __restrict__ A,
                                const float* __restrict__ W,
                                const float* __restrict__ bias,
                                float* __restrict__ C,
                                int M, int K, int Ncols, int act) {
    __shared__ float As[8][128];
    __shared__ float Bs[8][128];
    const int tid = threadIdx.x;
    const int tx = tid & 15, ty = tid >> 4;
    const int m0 = blockIdx.y * 128, n0 = blockIdx.x * 128;

    const int a_row = tid >> 1, a_col = (tid & 1) * 4;
    const int b_row = tid >> 5, b_col = (tid & 31) * 4;

    float acc[8][8] = {};

    for (int k0 = 0; k0 < K; k0 += 8) {
        float4 av = make_float4(0.f, 0.f, 0.f, 0.f);
        if (m0 + a_row < M)
            av = *(const float4*)(A + (size_t)(m0 + a_row) * K + k0 + a_col);
        As[a_col + 0][a_row] = av.x;
        As[a_col + 1][a_row] = av.y;
        As[a_col + 2][a_row] = av.z;
        As[a_col + 3][a_row] = av.w;

        *(float4*)&Bs[b_row][b_col] =
            *(const float4*)(W + (size_t)(k0 + b_row) * Ncols + n0 + b_col);
        __syncthreads();

#pragma unroll
        for (int kk = 0; kk < 8; kk++) {
            float a[8], b[8];
            *(float4*)(a)     = *(const float4*)&As[kk][ty * 8];
            *(float4*)(a + 4) = *(const float4*)&As[kk][ty * 8 + 4];
            *(float4*)(b)     = *(const float4*)&Bs[kk][tx * 8];
            *(float4*)(b + 4) = *(const float4*)&Bs[kk][tx * 8 + 4];
#pragma unroll
            for (int i = 0; i < 8; i++)
#pragma unroll
                for (int j = 0; j < 8; j++)
                    acc[i][j] += a[i] * b[j];
        }
        __syncthreads();
    }

    float bb[8] = {};
    if (bias) {
        *(float4*)(bb)     = *(const float4*)(bias + n0 + tx * 8);
        *(float4*)(bb + 4) = *(const float4*)(bias + n0 + tx * 8 + 4);
    }

#pragma unroll
    for (int i = 0; i < 8; i++) {
        int m = m0 + ty * 8 + i;
        if (m >= M) break;
        float* crow = C + (size_t)m * Ncols + n0 + tx * 8;
#pragma unroll
        for (int jj = 0; jj < 8; jj += 4) {
            float4 v;
            v.x = acc[i][jj + 0] + bb[jj + 0];
            v.y = acc[i][jj + 1] + bb[jj + 1];
            v.z = acc[i][jj + 2] + bb[jj + 2];
            v.w = acc[i][jj + 3] + bb[jj + 3];
            if (act) {
                v.x = fmaxf(v.x, 0.f); v.y = fmaxf(v.y, 0.f);
                v.z = fmaxf(v.z, 0.f); v.w = fmaxf(v.w, 0.f);
            }
            *(float4*)(crow + jj) = v;
        }
    }
}

// ---------------- small SGEMM (64x64 tile) for gat3 ------------------------
__global__ void sgemm_kernel(const float* __restrict__ A,
                             const float* __restrict__ W,
                             const float* __restrict__ bias,
                             float* __restrict__ C,
                             int M, int K, int Ncols, int act) {
    __shared__ float As[16][64];
    __shared__ float Ws[16][64];
    const int tid = threadIdx.x;
    const int tx = tid & 15, ty = tid >> 4;
    const int m0 = blockIdx.y * 64, n0 = blockIdx.x * 64;
    const int ar = tid >> 2, ac = (tid & 3) * 4;
    const int wr = tid >> 4, wc = (tid & 15) * 4;
    float acc[4][4] = {};
    for (int k0 = 0; k0 < K; k0 += 16) {
        float4 av = make_float4(0.f, 0.f, 0.f, 0.f);
        if (m0 + ar < M)
            av = *(const float4*)(A + (size_t)(m0 + ar) * K + k0 + ac);
        As[ac + 0][ar] = av.x;
        As[ac + 1][ar] = av.y;
        As[ac + 2][ar] = av.z;
        As[ac + 3][ar] = av.w;
        *(float4*)&Ws[wr][wc] = *(const float4*)(W + (size_t)(k0 + wr) * Ncols + n0 + wc);
        __syncthreads();
#pragma unroll
        for (int kk = 0; kk < 16; kk++) {
            float4 a = *(const float4*)&As[kk][ty * 4];
            float4 b = *(const float4*)&Ws[kk][tx * 4];
            float am[4] = {a.x, a.y, a.z, a.w};
            float bm[4] = {b.x, b.y, b.z, b.w};
#pragma unroll
            for (int i = 0; i < 4; i++)
#pragma unroll
                for (int j = 0; j < 4; j++)
                    acc[i][j] += am[i] * bm[j];
        }
        __syncthreads();
    }
    float4 bb = make_float4(0.f, 0.f, 0.f, 0.f);
    if (bias) bb = *(const float4*)(bias + n0 + tx * 4);
#pragma unroll
    for (int i = 0; i < 4; i++) {
        int m = m0 + ty * 4 + i;
        if (m >= M) break;
        float4 v;
        v.x = acc[i][0] + bb.x;
        v.y = acc[i][1] + bb.y;
        v.z = acc[i][2] + bb.z;
        v.w = acc[i][3] + bb.w;
        if (act) {
            v.x = fmaxf(v.x, 0.f); v.y = fmaxf(v.y, 0.f);
            v.z = fmaxf(v.z, 0.f); v.w = fmaxf(v.w, 0.f);
        }
        *(float4*)(C + (size_t)m * Ncols + n0 + tx * 4) = v;
    }
}

// ---------------- per-node attention scores: warp per (n,h), D=64 ----------
template <int H>
__global__ void attn_scores_kernel(const float* __restrict__ xh,
                                   const float* __restrict__ a_src,
                                   const float* __restrict__ a_dst,
                                   float* __restrict__ ssrc,
                                   float* __restrict__ sdst) {
    int warp = (blockIdx.x * blockDim.x + threadIdx.x) >> 5;
    int lane = threadIdx.x & 31;
    if (warp >= NN * H) return;
    int n = warp / H, h = warp % H;
    const float* row = xh + (size_t)n * H * 64 + h * 64;
    float x0 = row[lane], x1 = row[lane + 32];
    float ps = x0 * a_src[h * 64 + lane] + x1 * a_src[h * 64 + lane + 32];
    float pd = x0 * a_dst[h * 64 + lane] + x1 * a_dst[h * 64 + lane + 32];
#pragma unroll
    for (int o = 16; o; o >>= 1) {
        ps += __shfl_xor_sync(0xffffffffu, ps, o);
        pd += __shfl_xor_sync(0xffffffffu, pd, o);
    }
    if (lane == 0) { ssrc[warp] = ps; sdst[warp] = pd; }
}

// ---------------- edge pass 1: exp(leaky_relu) + segment-sum z -------------
template <int H>
__global__ void edge_softmax_num(const int* __restrict__ ei,
                                 const float* __restrict__ ssrc,
                                 const float* __restrict__ sdst,
                                 float* __restrict__ expe,
                                 float* __restrict__ z) {
    int e = blockIdx.x * blockDim.x + threadIdx.x;
    if (e >= NT) return;
    int s, d;
    if (e < NE) { s = ei[e]; d = ei[NE + e]; }
    else        { s = d = e - NE; }
    if constexpr (H == 4) {
        float4 ss = *(const float4*)(ssrc + s * 4);
        float4 sd = *(const float4*)(sdst + d * 4);
        float4 v;
        v.x = ss.x + sd.x; v.y = ss.y + sd.y; v.z = ss.z + sd.z; v.w = ss.w + sd.w;
        v.x = expf(v.x > 0.f ? v.x : 0.2f * v.x);
        v.y = expf(v.y > 0.f ? v.y : 0.2f * v.y);
        v.z = expf(v.z > 0.f ? v.z : 0.2f * v.z);
        v.w = expf(v.w > 0.f ? v.w : 0.2f * v.w);
        *(float4*)(expe + (size_t)e * 4) = v;
        red_add4(z + d * 4, v);
    } else if constexpr (H == 2) {
        float2 ss = *(const float2*)(ssrc + s * 2);
        float2 sd = *(const float2*)(sdst + d * 2);
        float2 v;
        v.x = ss.x + sd.x; v.y = ss.y + sd.y;
        v.x = expf(v.x > 0.f ? v.x : 0.2f * v.x);
        v.y = expf(v.y > 0.f ? v.y : 0.2f * v.y);
        *(float2*)(expe + (size_t)e * 2) = v;
        red_add2(z + d * 2, v);
    } else {
        float v = ssrc[s] + sdst[d];
        v = expf(v > 0.f ? v : 0.2f * v);
        expe[e] = v;
        atomicAdd(&z[d], v);
    }
}

// ---------------- edge pass 2: out[dst] += xh[src] * alpha (float4) --------
template <int H>
__global__ void edge_aggregate(const int* __restrict__ ei,
                               const float* __restrict__ xh,
                               const float* __restrict__ expe,
                               const float* __restrict__ z,
                               float* __restrict__ out) {
    const int TPE = H * 16;          // threads per edge (each does one float4)
    const int EPB = 256 / TPE;       // edges per block
    int lane = threadIdx.x % TPE;
    int el   = threadIdx.x / TPE;
    int e = blockIdx.x * EPB + el;
    if (e >= NT) return;
    int s, d;
    if (e < NE) { s = ei[e]; d = ei[NE + e]; }
    else        { s = d = e - NE; }
    int h = lane >> 4;
    float alpha = expe[(size_t)e * H + h] / z[d * H + h];
    float4 xv = ((const float4*)xh)[(size_t)s * TPE + lane];
    float4 v;
    v.x = xv.x * alpha; v.y = xv.y * alpha; v.z = xv.z * alpha; v.w = xv.w * alpha;
    red_add4(out + (size_t)d * TPE * 4 + lane * 4, v);
}

// ---------------- finalize kernels -----------------------------------------
__global__ void final_concat_elu(float* __restrict__ io,
                                 const float* __restrict__ b, int C) {
    int i = blockIdx.x * blockDim.x + threadIdx.x;
    if (i >= NN * C) return;
    float v = io[i] + b[i % C];
    io[i] = v > 0.f ? v : expm1f(v);
}

__global__ void final_mean2_elu(const float* __restrict__ acc,
                                const float* __restrict__ b,
                                float* __restrict__ out) {
    int i = blockIdx.x * blockDim.x + threadIdx.x;
    if (i >= NN * 64) return;
    int n = i >> 6, d = i & 63;
    float v = 0.5f * (acc[n * 128 + d] + acc[n * 128 + 64 + d]) + b[d];
    out[i] = v > 0.f ? v : expm1f(v);
}

__global__ void final_out_kernel(const float* __restrict__ acc,
                                 const float* __restrict__ b,
                                 float* __restrict__ out) {
    int i = blockIdx.x * blockDim.x + threadIdx.x;
    if (i >= NN * 64) return;
    out[i] = acc[i] + b[i & 63];
}

// ---------------------------------------------------------------------------
static inline void run_gemm128(const float* A, const float* W, const float* bias,
                               float* C, int M, int K, int Ncols, int act) {
    dim3 grid(Ncols / 128, (M + 127) / 128);
    sgemm128_kernel<<<grid, 256>>>(A, W, bias, C, M, K, Ncols, act);
}
static inline void run_gemm64(const float* A, const float* W, const float* bias,
                              float* C, int M, int K, int Ncols, int act) {
    dim3 grid(Ncols / 64, (M + 63) / 64);
    sgemm_kernel<<<grid, 256>>>(A, W, bias, C, M, K, Ncols, act);
}

extern "C" void kernel_launch(void* const* d_in, const int* in_sizes, int n_in,
                              void* d_out, int out_size) {
    const float* x    = (const float*)d_in[0];
    const int*   ei   = (const int*)d_in[1];
    const float* w1   = (const float*)d_in[2];
    const float* b1   = (const float*)d_in[3];
    const float* w2   = (const float*)d_in[4];
    const float* b2   = (const float*)d_in[5];
    const float* g1w  = (const float*)d_in[6];
    const float* g1as = (const float*)d_in[7];
    const float* g1ad = (const float*)d_in[8];
    const float* g1b  = (const float*)d_in[9];
    const float* g2w  = (const float*)d_in[10];
    const float* g2as = (const float*)d_in[11];
    const float* g2ad = (const float*)d_in[12];
    const float* g2b  = (const float*)d_in[13];
    const float* g3w  = (const float*)d_in[14];
    const float* g3as = (const float*)d_in[15];
    const float* g3ad = (const float*)d_in[16];
    const float* g3b  = (const float*)d_in[17];
    float* out = (float*)d_out;

    float *bufA, *bufB, *bufC, *ssrc, *sdst, *z, *expe;
    cudaGetSymbolAddress((void**)&bufA, g_bufA);
    cudaGetSymbolAddress((void**)&bufB, g_bufB);
    cudaGetSymbolAddress((void**)&bufC, g_bufC);
    cudaGetSymbolAddress((void**)&ssrc, g_ssrc);
    cudaGetSymbolAddress((void**)&sdst, g_sdst);
    cudaGetSymbolAddress((void**)&z, g_z);
    cudaGetSymbolAddress((void**)&expe, g_expe);

    const int M = NN;

    // ---------------- MLP ----------------
    run_gemm128(x,    w1, b1, bufC, M, 256, 128, 1);   // h0 = relu(x@w1+b1)
    run_gemm128(bufC, w2, b2, bufB, M, 128, 128, 1);   // h1 = relu(h0@w2+b2)

    // ---------------- GAT1: H=4, D=64, concat, in=bufB(128) -----------------
    run_gemm128(bufB, g1w, nullptr, bufA, M, 128, 256, 0);       // xh -> bufA
    {
        int warps = NN * 4;
        attn_scores_kernel<4><<<(warps * 32 + 255) / 256, 256>>>(bufA, g1as, g1ad, ssrc, sdst);
        cudaMemsetAsync(z, 0, (size_t)NN * 4 * sizeof(float));
        edge_softmax_num<4><<<(NT + 255) / 256, 256>>>(ei, ssrc, sdst, expe, z);
        cudaMemsetAsync(bufC, 0, (size_t)NN * 256 * sizeof(float));
        edge_aggregate<4><<<(NT + 3) / 4, 256>>>(ei, bufA, expe, z, bufC);
        final_concat_elu<<<(NN * 256 + 255) / 256, 256>>>(bufC, g1b, 256);  // out1 in bufC
    }

    // ---------------- GAT2: H=2, D=64, mean, in=bufC(256) -------------------
    run_gemm128(bufC, g2w, nullptr, bufB, M, 256, 128, 0);       // xh -> bufB
    {
        int warps = NN * 2;
        attn_scores_kernel<2><<<(warps * 32 + 255) / 256, 256>>>(bufB, g2as, g2ad, ssrc, sdst);
        cudaMemsetAsync(z, 0, (size_t)NN * 2 * sizeof(float));
        edge_softmax_num<2><<<(NT + 255) / 256, 256>>>(ei, ssrc, sdst, expe, z);
        cudaMemsetAsync(bufA, 0, (size_t)NN * 128 * sizeof(float));
        edge_aggregate<2><<<(NT + 7) / 8, 256>>>(ei, bufB, expe, z, bufA);
        final_mean2_elu<<<(NN * 64 + 255) / 256, 256>>>(bufA, g2b, bufC);   // h3 in bufC[N,64]
    }

    // ---------------- GAT3: H=1, D=64, mean(identity), in=bufC(64) ----------
    run_gemm64(bufC, g3w, nullptr, bufB, M, 64, 64, 0);          // xh -> bufB
    {
        int warps = NN * 1;
        attn_scores_kernel<1><<<(warps * 32 + 255) / 256, 256>>>(bufB, g3as, g3ad, ssrc, sdst);
        cudaMemsetAsync(z, 0, (size_t)NN * 1 * sizeof(float));
        edge_softmax_num<1><<<(NT + 255) / 256, 256>>>(ei, ssrc, sdst, expe, z);
        cudaMemsetAsync(bufA, 0, (size_t)NN * 64 * sizeof(float));
        edge_aggregate<1><<<(NT + 15) / 16, 256>>>(ei, bufB, expe, z, bufA);
        final_out_kernel<<<(NN * 64 + 255) / 256, 256>>>(bufA, g3b, out);
    }
}

// round 4
// speedup vs baseline: 2.9692x; 1.4771x over previous
#include <cuda_runtime.h>
#include <math.h>

#define NN 50000
#define NE 800000
#define NT (NN + NE)   // edges incl. self loops
#define MAXC 256

// ---------------- scratch (static device globals; allowed) ----------------
__device__ float g_bufA[NN * MAXC];   // 51.2 MB
__device__ float g_bufB[NN * MAXC];   // 51.2 MB
__device__ float g_bufC[NN * MAXC];   // 51.2 MB
__device__ float g_ssrc[NN * 4];
__device__ float g_sdst[NN * 4];
__device__ int   g_deg[NN];
__device__ int   g_offs[NN + 1];
__device__ int   g_cursor[NN];
__device__ int   g_csr[NT];

// ---------------- CSR build ------------------------------------------------
__global__ void deg_count_kernel(const int* __restrict__ ei, int* __restrict__ deg) {
    int e = blockIdx.x * blockDim.x + threadIdx.x;
    if (e >= NT) return;
    int d = (e < NE) ? ei[NE + e] : (e - NE);
    atomicAdd(&deg[d], 1);
}

// single-block exclusive scan over NN degrees -> offs + cursor
__global__ void scan_kernel(const int* __restrict__ deg,
                            int* __restrict__ offs,
                            int* __restrict__ cursor) {
    __shared__ int sh[1024];
    const int tid = threadIdx.x;
    const int CH = (NN + 1023) / 1024;   // 49
    const int base = tid * CH;
    int s = 0;
    for (int i = 0; i < CH; i++) {
        int idx = base + i;
        if (idx < NN) s += deg[idx];
    }
    sh[tid] = s;
    __syncthreads();
    int mine = s;
    for (int off = 1; off < 1024; off <<= 1) {
        int t2 = (tid >= off) ? sh[tid - off] : 0;
        __syncthreads();
        sh[tid] += t2;
        __syncthreads();
    }
    int run = sh[tid] - mine;   // exclusive prefix
    for (int i = 0; i < CH; i++) {
        int idx = base + i;
        if (idx < NN) {
            offs[idx] = run;
            cursor[idx] = run;
            run += deg[idx];
        }
    }
    if (tid == 1023) offs[NN] = run;
}

__global__ void csr_fill_kernel(const int* __restrict__ ei,
                                int* __restrict__ cursor,
                                int* __restrict__ csr) {
    int e = blockIdx.x * blockDim.x + threadIdx.x;
    if (e >= NT) return;
    int s, d;
    if (e < NE) { s = ei[e]; d = ei[NE + e]; }
    else        { s = d = e - NE; }
    int pos = atomicAdd(&cursor[d], 1);
    csr[pos] = s;
}

// ---------------- big tiled SGEMM: 128x128 tile, BK=8, 8x8 microtile -------
__global__ void sgemm128_kernel(const float* __restrict__ A,
                                const float* __restrict__ W,
                                const float* __restrict__ bias,
                                float* __restrict__ C,
                                int M, int K, int Ncols, int act) {
    __shared__ float As[8][128];
    __shared__ float Bs[8][128];
    const int tid = threadIdx.x;
    const int tx = tid & 15, ty = tid >> 4;
    const int m0 = blockIdx.y * 128, n0 = blockIdx.x * 128;

    const int a_row = tid >> 1, a_col = (tid & 1) * 4;
    const int b_row = tid >> 5, b_col = (tid & 31) * 4;

    float acc[8][8] = {};

    for (int k0 = 0; k0 < K; k0 += 8) {
        float4 av = make_float4(0.f, 0.f, 0.f, 0.f);
        if (m0 + a_row < M)
            av = *(const float4*)(A + (size_t)(m0 + a_row) * K + k0 + a_col);
        As[a_col + 0][a_row] = av.x;
        As[a_col + 1][a_row] = av.y;
        As[a_col + 2][a_row] = av.z;
        As[a_col + 3][a_row] = av.w;

        *(float4*)&Bs[b_row][b_col] =
            *(const float4*)(W + (size_t)(k0 + b_row) * Ncols + n0 + b_col);
        __syncthreads();

#pragma unroll
        for (int kk = 0; kk < 8; kk++) {
            float a[8], b[8];
            *(float4*)(a)     = *(const float4*)&As[kk][ty * 8];
            *(float4*)(a + 4) = *(const float4*)&As[kk][ty * 8 + 4];
            *(float4*)(b)     = *(const float4*)&Bs[kk][tx * 8];
            *(float4*)(b + 4) = *(const float4*)&Bs[kk][tx * 8 + 4];
#pragma unroll
            for (int i = 0; i < 8; i++)
#pragma unroll
                for (int j = 0; j < 8; j++)
                    acc[i][j] += a[i] * b[j];
        }
        __syncthreads();
    }

    float bb[8] = {};
    if (bias) {
        *(float4*)(bb)     = *(const float4*)(bias + n0 + tx * 8);
        *(float4*)(bb + 4) = *(const float4*)(bias + n0 + tx * 8 + 4);
    }

#pragma unroll
    for (int i = 0; i < 8; i++) {
        int m = m0 + ty * 8 + i;
        if (m >= M) break;
        float* crow = C + (size_t)m * Ncols + n0 + tx * 8;
#pragma unroll
        for (int jj = 0; jj < 8; jj += 4) {
            float4 v;
            v.x = acc[i][jj + 0] + bb[jj + 0];
            v.y = acc[i][jj + 1] + bb[jj + 1];
            v.z = acc[i][jj + 2] + bb[jj + 2];
            v.w = acc[i][jj + 3] + bb[jj + 3];
            if (act) {
                v.x = fmaxf(v.x, 0.f); v.y = fmaxf(v.y, 0.f);
                v.z = fmaxf(v.z, 0.f); v.w = fmaxf(v.w, 0.f);
            }
            *(float4*)(crow + jj) = v;
        }
    }
}

// ---------------- small SGEMM (64x64 tile) for gat3 ------------------------
__global__ void sgemm_kernel(const float* __restrict__ A,
                             const float* __restrict__ W,
                             const float* __restrict__ bias,
                             float* __restrict__ C,
                             int M, int K, int Ncols, int act) {
    __shared__ float As[16][64];
    __shared__ float Ws[16][64];
    const int tid = threadIdx.x;
    const int tx = tid & 15, ty = tid >> 4;
    const int m0 = blockIdx.y * 64, n0 = blockIdx.x * 64;
    const int ar = tid >> 2, ac = (tid & 3) * 4;
    const int wr = tid >> 4, wc = (tid & 15) * 4;
    float acc[4][4] = {};
    for (int k0 = 0; k0 < K; k0 += 16) {
        float4 av = make_float4(0.f, 0.f, 0.f, 0.f);
        if (m0 + ar < M)
            av = *(const float4*)(A + (size_t)(m0 + ar) * K + k0 + ac);
        As[ac + 0][ar] = av.x;
        As[ac + 1][ar] = av.y;
        As[ac + 2][ar] = av.z;
        As[ac + 3][ar] = av.w;
        *(float4*)&Ws[wr][wc] = *(const float4*)(W + (size_t)(k0 + wr) * Ncols + n0 + wc);
        __syncthreads();
#pragma unroll
        for (int kk = 0; kk < 16; kk++) {
            float4 a = *(const float4*)&As[kk][ty * 4];
            float4 b = *(const float4*)&Ws[kk][tx * 4];
            float am[4] = {a.x, a.y, a.z, a.w};
            float bm[4] = {b.x, b.y, b.z, b.w};
#pragma unroll
            for (int i = 0; i < 4; i++)
#pragma unroll
                for (int j = 0; j < 4; j++)
                    acc[i][j] += am[i] * bm[j];
        }
        __syncthreads();
    }
    float4 bb = make_float4(0.f, 0.f, 0.f, 0.f);
    if (bias) bb = *(const float4*)(bias + n0 + tx * 4);
#pragma unroll
    for (int i = 0; i < 4; i++) {
        int m = m0 + ty * 4 + i;
        if (m >= M) break;
        float4 v;
        v.x = acc[i][0] + bb.x;
        v.y = acc[i][1] + bb.y;
        v.z = acc[i][2] + bb.z;
        v.w = acc[i][3] + bb.w;
        if (act) {
            v.x = fmaxf(v.x, 0.f); v.y = fmaxf(v.y, 0.f);
            v.z = fmaxf(v.z, 0.f); v.w = fmaxf(v.w, 0.f);
        }
        *(float4*)(C + (size_t)m * Ncols + n0 + tx * 4) = v;
    }
}

// ---------------- per-node attention scores: warp per (n,h), D=64 ----------
template <int H>
__global__ void attn_scores_kernel(const float* __restrict__ xh,
                                   const float* __restrict__ a_src,
                                   const float* __restrict__ a_dst,
                                   float* __restrict__ ssrc,
                                   float* __restrict__ sdst) {
    int warp = (blockIdx.x * blockDim.x + threadIdx.x) >> 5;
    int lane = threadIdx.x & 31;
    if (warp >= NN * H) return;
    int n = warp / H, h = warp % H;
    const float* row = xh + (size_t)n * H * 64 + h * 64;
    float x0 = row[lane], x1 = row[lane + 32];
    float ps = x0 * a_src[h * 64 + lane] + x1 * a_src[h * 64 + lane + 32];
    float pd = x0 * a_dst[h * 64 + lane] + x1 * a_dst[h * 64 + lane + 32];
#pragma unroll
    for (int o = 16; o; o >>= 1) {
        ps += __shfl_xor_sync(0xffffffffu, ps, o);
        pd += __shfl_xor_sync(0xffffffffu, pd, o);
    }
    if (lane == 0) { ssrc[warp] = ps; sdst[warp] = pd; }
}

// ---------------- fused CSR aggregate --------------------------------------
// MODE 0: concat + bias + ELU   (GAT1, H=4, out 256)
// MODE 1: mean-2 heads + bias + ELU (GAT2, H=2, out 64)
// MODE 2: plain + bias          (GAT3, H=1, out 64)
template <int H, int MODE>
__global__ void __launch_bounds__(128)
gat_aggregate(const int* __restrict__ offs,
              const int* __restrict__ csr,
              const float* __restrict__ xh,
              const float* __restrict__ ssrc,
              const float* __restrict__ sdst,
              const float* __restrict__ bias,
              float* __restrict__ out) {
    const int TPN = H * 16;          // threads per node (one float4 each)
    const int NPB = 128 / TPN;       // nodes per block
    const int t = threadIdx.x % TPN;
    const int n = blockIdx.x * NPB + threadIdx.x / TPN;   // NN divisible by NPB
    const int h = t >> 4;

    const float sd = sdst[n * H + h];
    const int beg = offs[n], end = offs[n + 1];

    float4 acc = make_float4(0.f, 0.f, 0.f, 0.f);
    float z = 0.f;

#pragma unroll 2
    for (int i = beg; i < end; i++) {
        int src = __ldg(&csr[i]);
        float v = ssrc[src * H + h] + sd;
        v = v > 0.f ? v : 0.2f * v;
        float e = __expf(v);
        float4 xv = *(const float4*)(xh + (size_t)src * (H * 64) + t * 4);
        acc.x += e * xv.x;
        acc.y += e * xv.y;
        acc.z += e * xv.z;
        acc.w += e * xv.w;
        z += e;
    }

    float inv = 1.f / z;
    acc.x *= inv; acc.y *= inv; acc.z *= inv; acc.w *= inv;

    if constexpr (MODE == 0) {
        float4 bb = *(const float4*)(bias + t * 4);
        float4 v;
        v.x = acc.x + bb.x; v.y = acc.y + bb.y;
        v.z = acc.z + bb.z; v.w = acc.w + bb.w;
        v.x = v.x > 0.f ? v.x : expm1f(v.x);
        v.y = v.y > 0.f ? v.y : expm1f(v.y);
        v.z = v.z > 0.f ? v.z : expm1f(v.z);
        v.w = v.w > 0.f ? v.w : expm1f(v.w);
        *(float4*)(out + (size_t)n * 256 + t * 4) = v;
    } else if constexpr (MODE == 1) {
        // TPN == 32: node group == exactly one warp; combine h=0 and h=1 lanes
        float4 o;
        o.x = __shfl_xor_sync(0xffffffffu, acc.x, 16);
        o.y = __shfl_xor_sync(0xffffffffu, acc.y, 16);
        o.z = __shfl_xor_sync(0xffffffffu, acc.z, 16);
        o.w = __shfl_xor_sync(0xffffffffu, acc.w, 16);
        if (h == 0) {
            float4 bb = *(const float4*)(bias + t * 4);
            float4 v;
            v.x = 0.5f * (acc.x + o.x) + bb.x;
            v.y = 0.5f * (acc.y + o.y) + bb.y;
            v.z = 0.5f * (acc.z + o.z) + bb.z;
            v.w = 0.5f * (acc.w + o.w) + bb.w;
            v.x = v.x > 0.f ? v.x : expm1f(v.x);
            v.y = v.y > 0.f ? v.y : expm1f(v.y);
            v.z = v.z > 0.f ? v.z : expm1f(v.z);
            v.w = v.w > 0.f ? v.w : expm1f(v.w);
            *(float4*)(out + (size_t)n * 64 + t * 4) = v;
        }
    } else {
        float4 bb = *(const float4*)(bias + t * 4);
        float4 v;
        v.x = acc.x + bb.x; v.y = acc.y + bb.y;
        v.z = acc.z + bb.z; v.w = acc.w + bb.w;
        *(float4*)(out + (size_t)n * 64 + t * 4) = v;
    }
}

// ---------------------------------------------------------------------------
static inline void run_gemm128(const float* A, const float* W, const float* bias,
                               float* C, int M, int K, int Ncols, int act) {
    dim3 grid(Ncols / 128, (M + 127) / 128);
    sgemm128_kernel<<<grid, 256>>>(A, W, bias, C, M, K, Ncols, act);
}
static inline void run_gemm64(const float* A, const float* W, const float* bias,
                              float* C, int M, int K, int Ncols, int act) {
    dim3 grid(Ncols / 64, (M + 63) / 64);
    sgemm_kernel<<<grid, 256>>>(A, W, bias, C, M, K, Ncols, act);
}

extern "C" void kernel_launch(void* const* d_in, const int* in_sizes, int n_in,
                              void* d_out, int out_size) {
    const float* x    = (const float*)d_in[0];
    const int*   ei   = (const int*)d_in[1];
    const float* w1   = (const float*)d_in[2];
    const float* b1   = (const float*)d_in[3];
    const float* w2   = (const float*)d_in[4];
    const float* b2   = (const float*)d_in[5];
    const float* g1w  = (const float*)d_in[6];
    const float* g1as = (const float*)d_in[7];
    const float* g1ad = (const float*)d_in[8];
    const float* g1b  = (const float*)d_in[9];
    const float* g2w  = (const float*)d_in[10];
    const float* g2as = (const float*)d_in[11];
    const float* g2ad = (const float*)d_in[12];
    const float* g2b  = (const float*)d_in[13];
    const float* g3w  = (const float*)d_in[14];
    const float* g3as = (const float*)d_in[15];
    const float* g3ad = (const float*)d_in[16];
    const float* g3b  = (const float*)d_in[17];
    float* out = (float*)d_out;

    float *bufA, *bufB, *bufC, *ssrc, *sdst;
    int *deg, *offs, *cursor, *csr;
    cudaGetSymbolAddress((void**)&bufA, g_bufA);
    cudaGetSymbolAddress((void**)&bufB, g_bufB);
    cudaGetSymbolAddress((void**)&bufC, g_bufC);
    cudaGetSymbolAddress((void**)&ssrc, g_ssrc);
    cudaGetSymbolAddress((void**)&sdst, g_sdst);
    cudaGetSymbolAddress((void**)&deg, g_deg);
    cudaGetSymbolAddress((void**)&offs, g_offs);
    cudaGetSymbolAddress((void**)&cursor, g_cursor);
    cudaGetSymbolAddress((void**)&csr, g_csr);

    const int M = NN;

    // ---------------- CSR build (once, reused by all 3 GAT layers) ----------
    cudaMemsetAsync(deg, 0, NN * sizeof(int));
    deg_count_kernel<<<(NT + 255) / 256, 256>>>(ei, deg);
    scan_kernel<<<1, 1024>>>(deg, offs, cursor);
    csr_fill_kernel<<<(NT + 255) / 256, 256>>>(ei, cursor, csr);

    // ---------------- MLP ----------------
    run_gemm128(x,    w1, b1, bufC, M, 256, 128, 1);   // h0 = relu(x@w1+b1)
    run_gemm128(bufC, w2, b2, bufB, M, 128, 128, 1);   // h1 = relu(h0@w2+b2)

    // ---------------- GAT1: H=4, D=64, concat, in=bufB(128) -----------------
    run_gemm128(bufB, g1w, nullptr, bufA, M, 128, 256, 0);       // xh1 -> bufA
    attn_scores_kernel<4><<<(NN * 4 * 32 + 255) / 256, 256>>>(bufA, g1as, g1ad, ssrc, sdst);
    gat_aggregate<4, 0><<<NN / 2, 128>>>(offs, csr, bufA, ssrc, sdst, g1b, bufC);

    // ---------------- GAT2: H=2, D=64, mean, in=bufC(256) -------------------
    run_gemm128(bufC, g2w, nullptr, bufB, M, 256, 128, 0);       // xh2 -> bufB
    attn_scores_kernel<2><<<(NN * 2 * 32 + 255) / 256, 256>>>(bufB, g2as, g2ad, ssrc, sdst);
    gat_aggregate<2, 1><<<NN / 4, 128>>>(offs, csr, bufB, ssrc, sdst, g2b, bufC);

    // ---------------- GAT3: H=1, D=64, mean(identity), in=bufC(64) ----------
    run_gemm64(bufC, g3w, nullptr, bufB, M, 64, 64, 0);          // xh3 -> bufB
    attn_scores_kernel<1><<<(NN * 1 * 32 + 255) / 256, 256>>>(bufB, g3as, g3ad, ssrc, sdst);
    gat_aggregate<1, 2><<<NN / 8, 128>>>(offs, csr, bufB, ssrc, sdst, g3b, out);
}

// round 5
// speedup vs baseline: 4.6789x; 1.5758x over previous
#include <cuda_runtime.h>
#include <math.h>
#include <stdint.h>

#define NN 50000
#define NE 800000
#define NT (NN + NE)   // edges incl. self loops
#define MAXC 256

// ---------------- scratch (static device globals; allowed) ----------------
__device__ float g_bufA[NN * MAXC];   // 51.2 MB
__device__ float g_bufB[NN * MAXC];   // 51.2 MB
__device__ float g_bufC[NN * MAXC];   // 51.2 MB
__device__ float g_ssrc[NN * 4];
__device__ float g_sdst[NN * 4];
__device__ int   g_deg[NN];
__device__ int   g_offs[NN + 1];
__device__ int   g_cursor[NN];
__device__ int   g_csr[NT];

// ---------------- CSR build ------------------------------------------------
__global__ void deg_count_kernel(const int* __restrict__ ei, int* __restrict__ deg) {
    int e = blockIdx.x * blockDim.x + threadIdx.x;
    if (e >= NT) return;
    int d = (e < NE) ? ei[NE + e] : (e - NE);
    atomicAdd(&deg[d], 1);
}

__global__ void scan_kernel(const int* __restrict__ deg,
                            int* __restrict__ offs,
                            int* __restrict__ cursor) {
    __shared__ int sh[1024];
    const int tid = threadIdx.x;
    const int CH = (NN + 1023) / 1024;   // 49
    const int base = tid * CH;
    int s = 0;
    for (int i = 0; i < CH; i++) {
        int idx = base + i;
        if (idx < NN) s += deg[idx];
    }
    sh[tid] = s;
    __syncthreads();
    int mine = s;
    for (int off = 1; off < 1024; off <<= 1) {
        int t2 = (tid >= off) ? sh[tid - off] : 0;
        __syncthreads();
        sh[tid] += t2;
        __syncthreads();
    }
    int run = sh[tid] - mine;   // exclusive prefix
    for (int i = 0; i < CH; i++) {
        int idx = base + i;
        if (idx < NN) {
            offs[idx] = run;
            cursor[idx] = run;
            run += deg[idx];
        }
    }
    if (tid == 1023) offs[NN] = run;
}

__global__ void csr_fill_kernel(const int* __restrict__ ei,
                                int* __restrict__ cursor,
                                int* __restrict__ csr) {
    int e = blockIdx.x * blockDim.x + threadIdx.x;
    if (e >= NT) return;
    int s, d;
    if (e < NE) { s = ei[e]; d = ei[NE + e]; }
    else        { s = d = e - NE; }
    int pos = atomicAdd(&cursor[d], 1);
    csr[pos] = s;
}

// ---------------- TF32 tensor-core GEMM ------------------------------------
// 128x128 block tile, BK=32, 8 warps (4x2), warp tile 32x64 (2x8 m16n8k8).
// Swizzled smem -> conflict-free fragment LDS. C = act(A@W + bias).
__device__ __forceinline__ uint32_t f2tf(float x) {
    uint32_t u;
    asm("cvt.rna.tf32.f32 %0, %1;" : "=r"(u) : "f"(x));
    return u;
}

__device__ __forceinline__ void mma_tf32(float* c, const uint32_t* a,
                                         uint32_t b0, uint32_t b1) {
    asm volatile(
        "mma.sync.aligned.m16n8k8.row.col.f32.tf32.tf32.f32 "
        "{%0,%1,%2,%3}, {%4,%5,%6,%7}, {%8,%9}, {%0,%1,%2,%3};"
        : "+f"(c[0]), "+f"(c[1]), "+f"(c[2]), "+f"(c[3])
        : "r"(a[0]), "r"(a[1]), "r"(a[2]), "r"(a[3]), "r"(b0), "r"(b1));
}

__global__ void __launch_bounds__(256, 2)
tf32_gemm_kernel(const float* __restrict__ A, const float* __restrict__ W,
                 const float* __restrict__ bias, float* __restrict__ C,
                 int M, int K, int N, int act) {
    __shared__ uint32_t sA[128 * 32];
    __shared__ uint32_t sB[32 * 128];
    const int tid = threadIdx.x;
    const int lane = tid & 31, warp = tid >> 5;
    const int wm = warp & 3, wn = warp >> 2;    // 4 warps along M, 2 along N
    const int gid = lane >> 2, tig = lane & 3;
    const int m0 = blockIdx.y * 128, n0 = blockIdx.x * 128;

    float acc[2][8][4];
#pragma unroll
    for (int i = 0; i < 2; i++)
#pragma unroll
        for (int j = 0; j < 8; j++)
#pragma unroll
            for (int q = 0; q < 4; q++) acc[i][j][q] = 0.f;

    for (int k0 = 0; k0 < K; k0 += 32) {
        // --- load A tile 128x32 (swizzle: col ^= (row&7)*4) ---
#pragma unroll
        for (int i = 0; i < 4; i++) {
            int idx = i * 256 + tid;
            int row = idx >> 3, kq = (idx & 7) * 4;
            float4 v = make_float4(0.f, 0.f, 0.f, 0.f);
            if (m0 + row < M)
                v = *(const float4*)(A + (size_t)(m0 + row) * K + k0 + kq);
            uint4 u;
            u.x = f2tf(v.x); u.y = f2tf(v.y); u.z = f2tf(v.z); u.w = f2tf(v.w);
            int sw = kq ^ ((row & 7) << 2);
            *(uint4*)&sA[row * 32 + sw] = u;
        }
        // --- load B tile 32x128 (swizzle: col ^= (k&3)*8) ---
#pragma unroll
        for (int i = 0; i < 4; i++) {
            int idx = i * 256 + tid;
            int kr = idx >> 5, nq = (idx & 31) * 4;
            float4 v = *(const float4*)(W + (size_t)(k0 + kr) * N + n0 + nq);
            uint4 u;
            u.x = f2tf(v.x); u.y = f2tf(v.y); u.z = f2tf(v.z); u.w = f2tf(v.w);
            int sw = nq ^ ((kr & 3) << 3);
            *(uint4*)&sB[kr * 128 + sw] = u;
        }
        __syncthreads();

#pragma unroll
        for (int kk = 0; kk < 32; kk += 8) {
            uint32_t a[2][4];
#pragma unroll
            for (int mt = 0; mt < 2; mt++) {
                int r = wm * 32 + mt * 16 + gid;   // r & 7 == gid
                int c0 = (kk + tig) ^ (gid << 2);
                int c1 = (kk + tig + 4) ^ (gid << 2);
                a[mt][0] = sA[r * 32 + c0];
                a[mt][1] = sA[(r + 8) * 32 + c0];
                a[mt][2] = sA[r * 32 + c1];
                a[mt][3] = sA[(r + 8) * 32 + c1];
            }
#pragma unroll
            for (int nt = 0; nt < 8; nt++) {
                int n = wn * 64 + nt * 8 + gid;
                int cs = n ^ (tig << 3);
                uint32_t b0 = sB[(kk + tig) * 128 + cs];
                uint32_t b1 = sB[(kk + tig + 4) * 128 + cs];
                mma_tf32(acc[0][nt], a[0], b0, b1);
                mma_tf32(acc[1][nt], a[1], b0, b1);
            }
        }
        __syncthreads();
    }

    // --- epilogue: bias + optional relu, float2 stores ---
#pragma unroll
    for (int mt = 0; mt < 2; mt++) {
        int r = m0 + wm * 32 + mt * 16 + gid;
#pragma unroll
        for (int nt = 0; nt < 8; nt++) {
            int cidx = n0 + wn * 64 + nt * 8 + tig * 2;
            float bv0 = 0.f, bv1 = 0.f;
            if (bias) { bv0 = bias[cidx]; bv1 = bias[cidx + 1]; }
            float2 v0, v1;
            v0.x = acc[mt][nt][0] + bv0;
            v0.y = acc[mt][nt][1] + bv1;
            v1.x = acc[mt][nt][2] + bv0;
            v1.y = acc[mt][nt][3] + bv1;
            if (act) {
                v0.x = fmaxf(v0.x, 0.f); v0.y = fmaxf(v0.y, 0.f);
                v1.x = fmaxf(v1.x, 0.f); v1.y = fmaxf(v1.y, 0.f);
            }
            if (r < M)     *(float2*)(C + (size_t)r * N + cidx) = v0;
            if (r + 8 < M) *(float2*)(C + (size_t)(r + 8) * N + cidx) = v1;
        }
    }
}

// ---------------- small SGEMM (64x64 tile) for gat3 ------------------------
__global__ void sgemm_kernel(const float* __restrict__ A,
                             const float* __restrict__ W,
                             const float* __restrict__ bias,
                             float* __restrict__ C,
                             int M, int K, int Ncols, int act) {
    __shared__ float As[16][64];
    __shared__ float Ws[16][64];
    const int tid = threadIdx.x;
    const int tx = tid & 15, ty = tid >> 4;
    const int m0 = blockIdx.y * 64, n0 = blockIdx.x * 64;
    const int ar = tid >> 2, ac = (tid & 3) * 4;
    const int wr = tid >> 4, wc = (tid & 15) * 4;
    float acc[4][4] = {};
    for (int k0 = 0; k0 < K; k0 += 16) {
        float4 av = make_float4(0.f, 0.f, 0.f, 0.f);
        if (m0 + ar < M)
            av = *(const float4*)(A + (size_t)(m0 + ar) * K + k0 + ac);
        As[ac + 0][ar] = av.x;
        As[ac + 1][ar] = av.y;
        As[ac + 2][ar] = av.z;
        As[ac + 3][ar] = av.w;
        *(float4*)&Ws[wr][wc] = *(const float4*)(W + (size_t)(k0 + wr) * Ncols + n0 + wc);
        __syncthreads();
#pragma unroll
        for (int kk = 0; kk < 16; kk++) {
            float4 a = *(const float4*)&As[kk][ty * 4];
            float4 b = *(const float4*)&Ws[kk][tx * 4];
            float am[4] = {a.x, a.y, a.z, a.w};
            float bm[4] = {b.x, b.y, b.z, b.w};
#pragma unroll
            for (int i = 0; i < 4; i++)
#pragma unroll
                for (int j = 0; j < 4; j++)
                    acc[i][j] += am[i] * bm[j];
        }
        __syncthreads();
    }
    float4 bb = make_float4(0.f, 0.f, 0.f, 0.f);
    if (bias) bb = *(const float4*)(bias + n0 + tx * 4);
#pragma unroll
    for (int i = 0; i < 4; i++) {
        int m = m0 + ty * 4 + i;
        if (m >= M) break;
        float4 v;
        v.x = acc[i][0] + bb.x;
        v.y = acc[i][1] + bb.y;
        v.z = acc[i][2] + bb.z;
        v.w = acc[i][3] + bb.w;
        if (act) {
            v.x = fmaxf(v.x, 0.f); v.y = fmaxf(v.y, 0.f);
            v.z = fmaxf(v.z, 0.f); v.w = fmaxf(v.w, 0.f);
        }
        *(float4*)(C + (size_t)m * Ncols + n0 + tx * 4) = v;
    }
}

// ---------------- per-node attention scores: warp per (n,h), D=64 ----------
template <int H>
__global__ void attn_scores_kernel(const float* __restrict__ xh,
                                   const float* __restrict__ a_src,
                                   const float* __restrict__ a_dst,
                                   float* __restrict__ ssrc,
                                   float* __restrict__ sdst) {
    int warp = (blockIdx.x * blockDim.x + threadIdx.x) >> 5;
    int lane = threadIdx.x & 31;
    if (warp >= NN * H) return;
    int n = warp / H, h = warp % H;
    const float* row = xh + (size_t)n * H * 64 + h * 64;
    float x0 = row[lane], x1 = row[lane + 32];
    float ps = x0 * a_src[h * 64 + lane] + x1 * a_src[h * 64 + lane + 32];
    float pd = x0 * a_dst[h * 64 + lane] + x1 * a_dst[h * 64 + lane + 32];
#pragma unroll
    for (int o = 16; o; o >>= 1) {
        ps += __shfl_xor_sync(0xffffffffu, ps, o);
        pd += __shfl_xor_sync(0xffffffffu, pd, o);
    }
    if (lane == 0) { ssrc[warp] = ps; sdst[warp] = pd; }
}

// ---------------- fused CSR aggregate --------------------------------------
template <int H, int MODE>
__global__ void __launch_bounds__(128)
gat_aggregate(const int* __restrict__ offs,
              const int* __restrict__ csr,
              const float* __restrict__ xh,
              const float* __restrict__ ssrc,
              const float* __restrict__ sdst,
              const float* __restrict__ bias,
              float* __restrict__ out) {
    const int TPN = H * 16;          // threads per node (one float4 each)
    const int NPB = 128 / TPN;       // nodes per block
    const int t = threadIdx.x % TPN;
    const int n = blockIdx.x * NPB + threadIdx.x / TPN;
    const int h = t >> 4;

    const float sd = sdst[n * H + h];
    const int beg = offs[n], end = offs[n + 1];

    float4 acc = make_float4(0.f, 0.f, 0.f, 0.f);
    float z = 0.f;

#pragma unroll 2
    for (int i = beg; i < end; i++) {
        int src = __ldg(&csr[i]);
        float v = ssrc[src * H + h] + sd;
        v = v > 0.f ? v : 0.2f * v;
        float e = __expf(v);
        float4 xv = *(const float4*)(xh + (size_t)src * (H * 64) + t * 4);
        acc.x += e * xv.x;
        acc.y += e * xv.y;
        acc.z += e * xv.z;
        acc.w += e * xv.w;
        z += e;
    }

    float inv = 1.f / z;
    acc.x *= inv; acc.y *= inv; acc.z *= inv; acc.w *= inv;

    if constexpr (MODE == 0) {
        float4 bb = *(const float4*)(bias + t * 4);
        float4 v;
        v.x = acc.x + bb.x; v.y = acc.y + bb.y;
        v.z = acc.z + bb.z; v.w = acc.w + bb.w;
        v.x = v.x > 0.f ? v.x : expm1f(v.x);
        v.y = v.y > 0.f ? v.y : expm1f(v.y);
        v.z = v.z > 0.f ? v.z : expm1f(v.z);
        v.w = v.w > 0.f ? v.w : expm1f(v.w);
        *(float4*)(out + (size_t)n * 256 + t * 4) = v;
    } else if constexpr (MODE == 1) {
        float4 o;
        o.x = __shfl_xor_sync(0xffffffffu, acc.x, 16);
        o.y = __shfl_xor_sync(0xffffffffu, acc.y, 16);
        o.z = __shfl_xor_sync(0xffffffffu, acc.z, 16);
        o.w = __shfl_xor_sync(0xffffffffu, acc.w, 16);
        if (h == 0) {
            float4 bb = *(const float4*)(bias + t * 4);
            float4 v;
            v.x = 0.5f * (acc.x + o.x) + bb.x;
            v.y = 0.5f * (acc.y + o.y) + bb.y;
            v.z = 0.5f * (acc.z + o.z) + bb.z;
            v.w = 0.5f * (acc.w + o.w) + bb.w;
            v.x = v.x > 0.f ? v.x : expm1f(v.x);
            v.y = v.y > 0.f ? v.y : expm1f(v.y);
            v.z = v.z > 0.f ? v.z : expm1f(v.z);
            v.w = v.w > 0.f ? v.w : expm1f(v.w);
            *(float4*)(out + (size_t)n * 64 + t * 4) = v;
        }
    } else {
        float4 bb = *(const float4*)(bias + t * 4);
        float4 v;
        v.x = acc.x + bb.x; v.y = acc.y + bb.y;
        v.z = acc.z + bb.z; v.w = acc.w + bb.w;
        *(float4*)(out + (size_t)n * 64 + t * 4) = v;
    }
}

// ---------------------------------------------------------------------------
static inline void run_tf32(const float* A, const float* W, const float* bias,
                            float* C, int M, int K, int N, int act) {
    dim3 grid(N / 128, (M + 127) / 128);
    tf32_gemm_kernel<<<grid, 256>>>(A, W, bias, C, M, K, N, act);
}
static inline void run_gemm64(const float* A, const float* W, const float* bias,
                              float* C, int M, int K, int Ncols, int act) {
    dim3 grid(Ncols / 64, (M + 63) / 64);
    sgemm_kernel<<<grid, 256>>>(A, W, bias, C, M, K, Ncols, act);
}

extern "C" void kernel_launch(void* const* d_in, const int* in_sizes, int n_in,
                              void* d_out, int out_size) {
    const float* x    = (const float*)d_in[0];
    const int*   ei   = (const int*)d_in[1];
    const float* w1   = (const float*)d_in[2];
    const float* b1   = (const float*)d_in[3];
    const float* w2   = (const float*)d_in[4];
    const float* b2   = (const float*)d_in[5];
    const float* g1w  = (const float*)d_in[6];
    const float* g1as = (const float*)d_in[7];
    const float* g1ad = (const float*)d_in[8];
    const float* g1b  = (const float*)d_in[9];
    const float* g2w  = (const float*)d_in[10];
    const float* g2as = (const float*)d_in[11];
    const float* g2ad = (const float*)d_in[12];
    const float* g2b  = (const float*)d_in[13];
    const float* g3w  = (const float*)d_in[14];
    const float* g3as = (const float*)d_in[15];
    const float* g3ad = (const float*)d_in[16];
    const float* g3b  = (const float*)d_in[17];
    float* out = (float*)d_out;

    float *bufA, *bufB, *bufC, *ssrc, *sdst;
    int *deg, *offs, *cursor, *csr;
    cudaGetSymbolAddress((void**)&bufA, g_bufA);
    cudaGetSymbolAddress((void**)&bufB, g_bufB);
    cudaGetSymbolAddress((void**)&bufC, g_bufC);
    cudaGetSymbolAddress((void**)&ssrc, g_ssrc);
    cudaGetSymbolAddress((void**)&sdst, g_sdst);
    cudaGetSymbolAddress((void**)&deg, g_deg);
    cudaGetSymbolAddress((void**)&offs, g_offs);
    cudaGetSymbolAddress((void**)&cursor, g_cursor);
    cudaGetSymbolAddress((void**)&csr, g_csr);

    const int M = NN;

    // ---------------- CSR build (once, reused by all 3 GAT layers) ----------
    cudaMemsetAsync(deg, 0, NN * sizeof(int));
    deg_count_kernel<<<(NT + 255) / 256, 256>>>(ei, deg);
    scan_kernel<<<1, 1024>>>(deg, offs, cursor);
    csr_fill_kernel<<<(NT + 255) / 256, 256>>>(ei, cursor, csr);

    // ---------------- MLP ----------------
    run_tf32(x,    w1, b1, bufC, M, 256, 128, 1);   // h0 = relu(x@w1+b1)
    run_tf32(bufC, w2, b2, bufB, M, 128, 128, 1);   // h1 = relu(h0@w2+b2)

    // ---------------- GAT1: H=4, D=64, concat, in=bufB(128) -----------------
    run_tf32(bufB, g1w, nullptr, bufA, M, 128, 256, 0);          // xh1 -> bufA
    attn_scores_kernel<4><<<(NN * 4 * 32 + 255) / 256, 256>>>(bufA, g1as, g1ad, ssrc, sdst);
    gat_aggregate<4, 0><<<NN / 2, 128>>>(offs, csr, bufA, ssrc, sdst, g1b, bufC);

    // ---------------- GAT2: H=2, D=64, mean, in=bufC(256) -------------------
    run_tf32(bufC, g2w, nullptr, bufB, M, 256, 128, 0);          // xh2 -> bufB
    attn_scores_kernel<2><<<(NN * 2 * 32 + 255) / 256, 256>>>(bufB, g2as, g2ad, ssrc, sdst);
    gat_aggregate<2, 1><<<NN / 4, 128>>>(offs, csr, bufB, ssrc, sdst, g2b, bufC);

    // ---------------- GAT3: H=1, D=64, mean(identity), in=bufC(64) ----------
    run_gemm64(bufC, g3w, nullptr, bufB, M, 64, 64, 0);          // xh3 -> bufB
    attn_scores_kernel<1><<<(NN * 1 * 32 + 255) / 256, 256>>>(bufB, g3as, g3ad, ssrc, sdst);
    gat_aggregate<1, 2><<<NN / 8, 128>>>(offs, csr, bufB, ssrc, sdst, g3b, out);
}